// round 13
// baseline (speedup 1.0000x reference)
#include <cuda_runtime.h>
#include <math.h>
#include <float.h>

#define BATCH 64
#define NCP   512
#define CPD   64
#define NF    256
#define WS    512
#define SD    128
#define HOP   256
#define NS    65536
#define KT    16             // truncated frame count (contribution <= 1e-14 rel)
#define RLEN  4352           // (KT-1)*HOP + WS

typedef unsigned long long ull;

// ---------------- packed f32x2 helpers (sm_103a FFMA2) ----------------
__device__ __forceinline__ ull pk2(float x, float y){
    ull r; asm("mov.b64 %0, {%1,%2};" : "=l"(r) : "f"(x), "f"(y)); return r;
}
__device__ __forceinline__ void ffma2(ull& d, ull a, ull b){
    asm("fma.rn.f32x2 %0, %1, %2, %0;" : "+l"(d) : "l"(a), "l"(b));
}
__device__ __forceinline__ float2 unpk(ull v){
    float2 r; asm("mov.b64 {%0,%1}, %2;" : "=f"(r.x), "=f"(r.y) : "l"(v)); return r;
}

// ---------------- cp.async helpers ----------------
__device__ __forceinline__ unsigned smem_u32(const void* p){
    return (unsigned)__cvta_generic_to_shared(p);
}
#define CP_ASYNC16(dst, src) \
    asm volatile("cp.async.cg.shared.global [%0], [%1], 16;" :: "r"(dst), "l"(src))
#define CP_COMMIT() asm volatile("cp.async.commit_group;")
#define CP_WAIT(n)  asm volatile("cp.async.wait_group %0;" :: "n"(n))

// ---------------- device scratch (no allocations, 256B-aligned) ----------
__device__ __align__(256) float g_R[CPD * RLEN];        // IR bank (1.1 MB)
__device__ __align__(256) int   g_ic[BATCH * 8];
__device__ __align__(256) int   g_ioff[BATCH * 8];
__device__ __align__(256) float g_iv[BATCH * 8];

__device__ __forceinline__ bool better(float va, int ia, float vb, int ib){
    return (va > vb) || (va == vb && ia < ib);
}

// dyn smem layout (floats) for the channel branch:
#define SM_PS   0                 // 512   proj row c
#define SM_PD   512               // 512   projD row c
#define SM_MALL 1024              // 16*128 m_k bank
#define SM_PART 3072              // 8*128 m0 warp partials
#define SM_CS0  4096              // 16*512 C sub-chunk buf 0
#define SM_CS1  12288             // 16*512 C sub-chunk buf 1
#define SM_QS   20480             // 16*512 Q tile
#define SM_TOT  28672             // floats -> 114688 bytes

// ============================================================================
// K1: mega kernel (128 blocks, 256 threads)
//   blocks 0..63  : per-batch select -> g_ic/g_ioff/g_iv
//   blocks 64..127: channel c: m0, projD row, recurrence, Q=m@C, fold -> g_R[c]
// ============================================================================
__global__ void __launch_bounds__(256) k_mega(
    const float* __restrict__ ctrl,
    const float* __restrict__ times,
    const float* __restrict__ lookup,
    const float* __restrict__ proj,
    const float* __restrict__ Amat,
    const float* __restrict__ Bm,
    const float* __restrict__ Cm,
    const float* __restrict__ Dm)
{
    extern __shared__ __align__(16) float dyn[];
    const int bx  = blockIdx.x;
    const int tid = threadIdx.x;

    if (bx >= BATCH){
        // ======================= channel branch =======================
        const int c = bx - BATCH;
        float* ps   = dyn + SM_PS;
        float* pd   = dyn + SM_PD;
        float* mall = dyn + SM_MALL;
        float* part = dyn + SM_PART;
        float* Qs   = dyn + SM_QS;

        if (tid < 128)
            *(float4*)&ps[tid * 4] = *(const float4*)&proj[(size_t)c * WS + tid * 4];
        __syncthreads();

        // --- m0 = ps @ B ---
        {
            const int kg = tid >> 5, lane = tid & 31;
            const int s4 = lane * 4;
            float a0 = 0.f, a1 = 0.f, a2 = 0.f, a3 = 0.f;
            #pragma unroll 8
            for (int kk = 0; kk < 64; kk++){
                int k = kg * 64 + kk;
                float pv = ps[k];
                float4 bv = *(const float4*)&Bm[(size_t)k * SD + s4];
                a0 += pv * bv.x; a1 += pv * bv.y; a2 += pv * bv.z; a3 += pv * bv.w;
            }
            float4 pv4 = { a0, a1, a2, a3 };
            *(float4*)&part[kg * SD + s4] = pv4;
        }
        __syncthreads();
        if (tid < 128){
            float m0 = 0.f;
            #pragma unroll
            for (int kg = 0; kg < 8; kg++) m0 += part[kg * SD + tid];
            mall[tid] = m0;
        }
        __syncthreads();

        // --- pd = ps @ D : 4 interleaved accumulator chains ---
        {
            const int j2 = tid * 2;
            ull d0 = 0ull, d1 = 0ull, d2 = 0ull, d3 = 0ull;
            #pragma unroll 4
            for (int k = 0; k < WS; k += 4){
                ffma2(d0, pk2(ps[k],     ps[k]),     *(const ull*)&Dm[(size_t)(k)     * WS + j2]);
                ffma2(d1, pk2(ps[k + 1], ps[k + 1]), *(const ull*)&Dm[(size_t)(k + 1) * WS + j2]);
                ffma2(d2, pk2(ps[k + 2], ps[k + 2]), *(const ull*)&Dm[(size_t)(k + 2) * WS + j2]);
                ffma2(d3, pk2(ps[k + 3], ps[k + 3]), *(const ull*)&Dm[(size_t)(k + 3) * WS + j2]);
            }
            float2 r0 = unpk(d0), r1 = unpk(d1), r2 = unpk(d2), r3 = unpk(d3);
            pd[j2]     = (r0.x + r1.x) + (r2.x + r3.x);
            pd[j2 + 1] = (r0.y + r1.y) + (r2.y + r3.y);
        }

        // --- recurrence (A column tid in regs, m via LDS.128) ---
        float a[SD];
        if (tid < 128){
            #pragma unroll
            for (int i = 0; i < SD; i++) a[i] = Amat[i * SD + tid];
        }
        __syncthreads();
        #pragma unroll 1
        for (int k = 1; k < KT; k++){
            if (tid < 128){
                const float* m = &mall[(k - 1) * SD];
                float d0 = 0.f, d1 = 0.f, d2 = 0.f, d3 = 0.f;
                #pragma unroll
                for (int i = 0; i < SD; i += 4){
                    float4 mv = *(const float4*)&m[i];
                    d0 += mv.x * a[i];
                    d1 += mv.y * a[i + 1];
                    d2 += mv.z * a[i + 2];
                    d3 += mv.w * a[i + 3];
                }
                mall[k * SD + tid] = (d0 + d1) + (d2 + d3);
            }
            __syncthreads();
        }

        // --- Q = mall @ C : 8 sub-chunks of 16 s-rows, cp.async depth-2 ---
        const int kg = tid >> 6;
        const int j0 = (tid & 63) * 8;
        const int k0 = kg * 4;
        ull acc[16];
        #pragma unroll
        for (int q = 0; q < 16; q++) acc[q] = 0ull;

        // per-thread load slice for a 16-row sub-chunk (2048 float4, 8/thread)
        const int ld_row  = tid >> 5;          // reused for q strides below
        (void)ld_row;

        // issue sub-chunk 0 into buf0
        {
            float* nxt = dyn + SM_CS0;
            #pragma unroll
            for (int q = 0; q < 8; q++){
                int idx  = q * 256 + tid;      // float4 index in 2048
                int row  = idx >> 7;           // 128 float4 per row
                int col4 = (idx & 127) * 4;
                CP_ASYNC16(smem_u32(&nxt[row * WS + col4]),
                           &Cm[(size_t)row * WS + col4]);
            }
            CP_COMMIT();
        }

        #pragma unroll 1
        for (int sc = 0; sc < 8; sc++){
            float* cur = dyn + ((sc & 1) ? SM_CS1 : SM_CS0);
            if (sc < 7){
                float* nxt = dyn + (((sc + 1) & 1) ? SM_CS1 : SM_CS0);
                const float* src = &Cm[(size_t)(sc + 1) * 16 * WS];
                #pragma unroll
                for (int q = 0; q < 8; q++){
                    int idx  = q * 256 + tid;
                    int row  = idx >> 7;
                    int col4 = (idx & 127) * 4;
                    CP_ASYNC16(smem_u32(&nxt[row * WS + col4]),
                               &src[(size_t)row * WS + col4]);
                }
                CP_COMMIT();
                CP_WAIT(1);                    // sub-chunk sc landed
            } else {
                CP_WAIT(0);
            }
            __syncthreads();
            #pragma unroll 4
            for (int s = 0; s < 16; s++){
                int sg = sc * 16 + s;
                ulonglong2 c01 = *(const ulonglong2*)&cur[s * WS + j0];
                ulonglong2 c23 = *(const ulonglong2*)&cur[s * WS + j0 + 4];
                #pragma unroll
                for (int kk = 0; kk < 4; kk++){
                    float mv = mall[(k0 + kk) * SD + sg];
                    ull p = pk2(mv, mv);
                    ffma2(acc[kk * 4 + 0], p, c01.x);
                    ffma2(acc[kk * 4 + 1], p, c01.y);
                    ffma2(acc[kk * 4 + 2], p, c23.x);
                    ffma2(acc[kk * 4 + 3], p, c23.y);
                }
            }
            __syncthreads();                   // before refilling this buffer at sc+2
        }
        #pragma unroll
        for (int kk = 0; kk < 4; kk++)
            #pragma unroll
            for (int jp = 0; jp < 4; jp++)
                *(ull*)&Qs[(k0 + kk) * WS + j0 + jp * 2] = acc[kk * 4 + jp];
        __syncthreads();
        Qs[tid]       += pd[tid];
        Qs[tid + 256] += pd[tid + 256];
        __syncthreads();

        // --- Hann fold -> g_R[c] ---
        const float W = 0.01227184630309f;   // 2*pi/512
        #pragma unroll
        for (int it = 0; it < 5; it++){
            int i4 = it * 256 + tid;
            if (i4 < RLEN / 4){
                int m  = i4 * 4;
                int k1 = m >> 8, j1 = m & 255;
                float c0 = __cosf((j1 + 0) * W);
                float c1 = __cosf((j1 + 1) * W);
                float c2 = __cosf((j1 + 2) * W);
                float c3 = __cosf((j1 + 3) * W);
                float4 o = {0.f, 0.f, 0.f, 0.f};
                if (k1 < KT){
                    float4 v1 = *(const float4*)&Qs[k1 * WS + j1];
                    o.x = 0.5f * (1.f - c0) * v1.x;
                    o.y = 0.5f * (1.f - c1) * v1.y;
                    o.z = 0.5f * (1.f - c2) * v1.z;
                    o.w = 0.5f * (1.f - c3) * v1.w;
                }
                if (k1 > 0){
                    float4 v2 = *(const float4*)&Qs[(k1 - 1) * WS + j1 + 256];
                    o.x += 0.5f * (1.f + c0) * v2.x;
                    o.y += 0.5f * (1.f + c1) * v2.y;
                    o.z += 0.5f * (1.f + c2) * v2.z;
                    o.w += 0.5f * (1.f + c3) * v2.w;
                }
                *(float4*)&g_R[(size_t)c * RLEN + m] = o;
            }
        }
        return;
    }

    // ======================= select branch =======================
    __shared__ __align__(16) float smV[256][8];
    __shared__ __align__(16) int   smI[256][8];
    __shared__ __align__(16) float sv[256];
    __shared__ __align__(16) int   si[256];
    __shared__ int   s_row, s_p;
    __shared__ float s_sum;
    const int b = bx;

    {
        float v0 = ctrl[b * NCP + tid];
        float v1 = ctrl[b * NCP + 256 + tid];
        float bv = v0; int bi = tid;
        if (better(v1, 256 + tid, bv, bi)){ bv = v1; bi = 256 + tid; }
        sv[tid] = bv; si[tid] = bi;
        for (int s = 128; s > 0; s >>= 1){
            __syncthreads();
            if (tid < s){
                float vo = sv[tid + s]; int io = si[tid + s];
                if (better(vo, io, sv[tid], si[tid])){ sv[tid] = vo; si[tid] = io; }
            }
        }
        __syncthreads();
        if (tid == 0) s_row = si[0];
        __syncthreads();
    }
    {
        sv[tid] = times[b * NF + tid]; si[tid] = tid;
        for (int s = 128; s > 0; s >>= 1){
            __syncthreads();
            if (tid < s){
                float vo = sv[tid + s]; int io = si[tid + s];
                if (better(vo, io, sv[tid], si[tid])){ sv[tid] = vo; si[tid] = io; }
            }
        }
        __syncthreads();
        if (tid == 0) s_p = si[0] * (NS / NF);
    }

    const float* row = lookup + (size_t)s_row * (CPD * NF);

    float tv[8]; int ti[8]; float es = 0.f;
    #pragma unroll
    for (int q = 0; q < 8; q++){ tv[q] = -FLT_MAX; ti[q] = 0x7fffffff; }
    for (int j = tid; j < CPD * NF; j += 256){
        float x = row[j];
        es += __expf(x);
        if (better(x, j, tv[7], ti[7])){
            tv[7] = x; ti[7] = j;
            #pragma unroll
            for (int q = 7; q > 0; q--){
                if (better(tv[q], ti[q], tv[q-1], ti[q-1])){
                    float fv = tv[q]; tv[q] = tv[q-1]; tv[q-1] = fv;
                    int   fi = ti[q]; ti[q] = ti[q-1]; ti[q-1] = fi;
                } else break;
            }
        }
    }
    #pragma unroll
    for (int q = 0; q < 8; q++){ smV[tid][q] = tv[q]; smI[tid][q] = ti[q]; }
    __syncthreads();
    sv[tid] = es;

    for (int s = 128; s > 0; s >>= 1){
        __syncthreads();
        if (tid < s){
            sv[tid] += sv[tid + s];
            int ia = 0, ib = 0;
            float ov[8]; int oi[8];
            #pragma unroll
            for (int t = 0; t < 8; t++){
                float va = smV[tid][ia];     int xa = smI[tid][ia];
                float vb = smV[tid + s][ib]; int xb = smI[tid + s][ib];
                bool pa = better(va, xa, vb, xb);
                ov[t] = pa ? va : vb; oi[t] = pa ? xa : xb;
                ia += pa ? 1 : 0; ib += pa ? 0 : 1;
            }
            #pragma unroll
            for (int t = 0; t < 8; t++){ smV[tid][t] = ov[t]; smI[tid][t] = oi[t]; }
        }
    }
    __syncthreads();
    if (tid == 0) s_sum = sv[0];
    __syncthreads();

    if (tid < 8){
        int idx = smI[0][tid];
        float val = __expf(smV[0][tid]) / s_sum;
        g_ic  [b * 8 + tid] = idx >> 8;
        g_ioff[b * 8 + tid] = s_p + (idx & 255) * HOP;
        g_iv  [b * 8 + tid] = val;
    }
}

// ============================================================================
// K2: out[b][n] = sum_i v_i * R[c_i][n - off_i]
//     2048 samples/block; unrolled 8-impulse loop with block-uniform guards
// ============================================================================
__global__ void __launch_bounds__(256) k_out(float* __restrict__ out){
    const int b   = blockIdx.y;
    const int tid = threadIdx.x;
    const int n0  = blockIdx.x * 2048;

    int   lc[8]; int loff[8]; float lv[8]; bool live[8];
    int any = 0;
    #pragma unroll
    for (int i = 0; i < 8; i++){
        loff[i] = __ldg(&g_ioff[b * 8 + i]);
        lc[i]   = __ldg(&g_ic  [b * 8 + i]);
        lv[i]   = __ldg(&g_iv  [b * 8 + i]);
        live[i] = (loff[i] < n0 + 2048) && (loff[i] + RLEN > n0);
        any    += live[i] ? 1 : 0;
    }

    #pragma unroll
    for (int q = 0; q < 2; q++){
        const int n = n0 + (q * 256 + tid) * 4;
        float4 acc = {0.f, 0.f, 0.f, 0.f};
        if (any){
            #pragma unroll
            for (int i = 0; i < 8; i++){
                if (live[i]){                        // block-uniform branch
                    int d = n - loff[i];
                    if (d >= 0 && d < RLEN){
                        float4 r = __ldg((const float4*)&g_R[(size_t)lc[i] * RLEN + d]);
                        float v = lv[i];
                        acc.x += v * r.x; acc.y += v * r.y;
                        acc.z += v * r.z; acc.w += v * r.w;
                    }
                }
            }
        }
        *(float4*)&out[(size_t)b * NS + n] = acc;
    }
}

// ============================================================================
extern "C" void kernel_launch(void* const* d_in, const int* in_sizes, int n_in,
                              void* d_out, int out_size)
{
    const float* ctrl   = (const float*)d_in[0];
    const float* times  = (const float*)d_in[1];
    const float* lookup = (const float*)d_in[2];
    const float* proj   = (const float*)d_in[3];
    const float* Amat   = (const float*)d_in[4];
    const float* Bm     = (const float*)d_in[5];
    const float* Cm     = (const float*)d_in[6];
    const float* Dm     = (const float*)d_in[7];
    float* out = (float*)d_out;
    (void)in_sizes; (void)n_in; (void)out_size;

    const int dynBytes = SM_TOT * sizeof(float);   // 114688 B
    cudaFuncSetAttribute(k_mega, cudaFuncAttributeMaxDynamicSharedMemorySize,
                         dynBytes);

    // Node 1: select (64 blocks) + full per-channel pipeline -> R (64 blocks)
    k_mega<<<128, 256, dynBytes>>>(ctrl, times, lookup, proj, Amat, Bm, Cm, Dm);

    // Node 2: shift-accumulate with register-resident live guards
    k_out<<<dim3(32, BATCH), 256>>>(out);
}

// round 14
// speedup vs baseline: 1.5486x; 1.5486x over previous
#include <cuda_runtime.h>
#include <math.h>
#include <float.h>

#define BATCH 64
#define NCP   512
#define CPD   64
#define NF    256
#define WS    512
#define SD    128
#define HOP   256
#define NS    65536
#define KT    12             // truncated frame count (rel contribution <= 3e-11)
#define RLEN  3328           // (KT-1)*HOP + WS

typedef unsigned long long ull;

// ---------------- packed f32x2 helpers (sm_103a FFMA2) ----------------
__device__ __forceinline__ ull pk2(float x, float y){
    ull r; asm("mov.b64 %0, {%1,%2};" : "=l"(r) : "f"(x), "f"(y)); return r;
}
__device__ __forceinline__ void ffma2(ull& d, ull a, ull b){
    asm("fma.rn.f32x2 %0, %1, %2, %0;" : "+l"(d) : "l"(a), "l"(b));
}
__device__ __forceinline__ float2 unpk(ull v){
    float2 r; asm("mov.b64 {%0,%1}, %2;" : "=f"(r.x), "=f"(r.y) : "l"(v)); return r;
}

// ---------------- device scratch (no allocations, 256B-aligned) ----------
__device__ __align__(256) float g_R[CPD * RLEN];        // IR bank (852 KB)
__device__ __align__(256) int   g_ic[BATCH * 8];
__device__ __align__(256) int   g_ioff[BATCH * 8];
__device__ __align__(256) float g_iv[BATCH * 8];

__device__ __forceinline__ bool better(float va, int ia, float vb, int ib){
    return (va > vb) || (va == vb && ia < ib);
}

// dyn smem layout (floats) for the channel branch:
#define SM_PS   0                 // 512   proj row c
#define SM_PD   512               // 512   projD row c
#define SM_MALL 1024              // 12*128 m_k bank (pad to 2048)
#define SM_PART 3072              // 8*128 m0 warp partials
#define SM_CS   4096              // 32*512 C chunk
#define SM_QS   20480             // 12*512 Q tile
#define SM_TOT  26624             // floats -> 106496 bytes

// ============================================================================
// K1: mega kernel (128 blocks, 256 threads)
//   blocks 0..63  : per-batch select -> g_ic/g_ioff/g_iv
//   blocks 64..127: channel c: m0, projD row, recurrence, Q=m@C, fold -> g_R[c]
// ============================================================================
__global__ void __launch_bounds__(256) k_mega(
    const float* __restrict__ ctrl,
    const float* __restrict__ times,
    const float* __restrict__ lookup,
    const float* __restrict__ proj,
    const float* __restrict__ Amat,
    const float* __restrict__ Bm,
    const float* __restrict__ Cm,
    const float* __restrict__ Dm)
{
    extern __shared__ __align__(16) float dyn[];
    const int bx  = blockIdx.x;
    const int tid = threadIdx.x;

    if (bx >= BATCH){
        // ======================= channel branch =======================
        const int c = bx - BATCH;
        float* ps   = dyn + SM_PS;
        float* pd   = dyn + SM_PD;
        float* mall = dyn + SM_MALL;
        float* part = dyn + SM_PART;
        float* Cs   = dyn + SM_CS;
        float* Qs   = dyn + SM_QS;

        if (tid < 128)
            *(float4*)&ps[tid * 4] = *(const float4*)&proj[(size_t)c * WS + tid * 4];
        __syncthreads();

        // --- m0 = ps @ B ---
        {
            const int kg = tid >> 5, lane = tid & 31;
            const int s4 = lane * 4;
            float a0 = 0.f, a1 = 0.f, a2 = 0.f, a3 = 0.f;
            #pragma unroll 8
            for (int kk = 0; kk < 64; kk++){
                int k = kg * 64 + kk;
                float pv = ps[k];
                float4 bv = *(const float4*)&Bm[(size_t)k * SD + s4];
                a0 += pv * bv.x; a1 += pv * bv.y; a2 += pv * bv.z; a3 += pv * bv.w;
            }
            float4 pv4 = { a0, a1, a2, a3 };
            *(float4*)&part[kg * SD + s4] = pv4;
        }
        __syncthreads();
        if (tid < 128){
            float m0 = 0.f;
            #pragma unroll
            for (int kg = 0; kg < 8; kg++) m0 += part[kg * SD + tid];
            mall[tid] = m0;
        }
        __syncthreads();

        // --- pd = ps @ D : 4 interleaved accumulator chains ---
        {
            const int j2 = tid * 2;
            ull d0 = 0ull, d1 = 0ull, d2 = 0ull, d3 = 0ull;
            #pragma unroll 4
            for (int k = 0; k < WS; k += 4){
                ffma2(d0, pk2(ps[k],     ps[k]),     *(const ull*)&Dm[(size_t)(k)     * WS + j2]);
                ffma2(d1, pk2(ps[k + 1], ps[k + 1]), *(const ull*)&Dm[(size_t)(k + 1) * WS + j2]);
                ffma2(d2, pk2(ps[k + 2], ps[k + 2]), *(const ull*)&Dm[(size_t)(k + 2) * WS + j2]);
                ffma2(d3, pk2(ps[k + 3], ps[k + 3]), *(const ull*)&Dm[(size_t)(k + 3) * WS + j2]);
            }
            float2 r0 = unpk(d0), r1 = unpk(d1), r2 = unpk(d2), r3 = unpk(d3);
            pd[j2]     = (r0.x + r1.x) + (r2.x + r3.x);
            pd[j2 + 1] = (r0.y + r1.y) + (r2.y + r3.y);
        }

        // --- recurrence (A column tid in regs, m via LDS.128) ---
        float a[SD];
        if (tid < 128){
            #pragma unroll
            for (int i = 0; i < SD; i++) a[i] = Amat[i * SD + tid];
        }
        __syncthreads();
        #pragma unroll 1
        for (int k = 1; k < KT; k++){
            if (tid < 128){
                const float* m = &mall[(k - 1) * SD];
                float d0 = 0.f, d1 = 0.f, d2 = 0.f, d3 = 0.f;
                #pragma unroll
                for (int i = 0; i < SD; i += 4){
                    float4 mv = *(const float4*)&m[i];
                    d0 += mv.x * a[i];
                    d1 += mv.y * a[i + 1];
                    d2 += mv.z * a[i + 2];
                    d3 += mv.w * a[i + 3];
                }
                mall[k * SD + tid] = (d0 + d1) + (d2 + d3);
            }
            __syncthreads();
        }

        // --- Q = mall @ C (4 staged chunks of 32 s-rows); kg covers 3 frames ---
        const int kg = tid >> 6;
        const int j0 = (tid & 63) * 8;
        const int k0 = kg * 3;
        ull acc[12];
        #pragma unroll
        for (int q = 0; q < 12; q++) acc[q] = 0ull;

        for (int ch = 0; ch < 4; ch++){
            #pragma unroll
            for (int q = 0; q < 16; q++){
                int idx  = q * 256 + tid;
                int row  = idx >> 7;
                int col4 = (idx & 127) * 4;
                *(float4*)&Cs[row * WS + col4] =
                    *(const float4*)&Cm[(size_t)(ch * 32 + row) * WS + col4];
            }
            __syncthreads();
            #pragma unroll 4
            for (int s = 0; s < 32; s++){
                int sg = ch * 32 + s;
                ulonglong2 c01 = *(const ulonglong2*)&Cs[s * WS + j0];
                ulonglong2 c23 = *(const ulonglong2*)&Cs[s * WS + j0 + 4];
                #pragma unroll
                for (int kk = 0; kk < 3; kk++){
                    float mv = mall[(k0 + kk) * SD + sg];
                    ull p = pk2(mv, mv);
                    ffma2(acc[kk * 4 + 0], p, c01.x);
                    ffma2(acc[kk * 4 + 1], p, c01.y);
                    ffma2(acc[kk * 4 + 2], p, c23.x);
                    ffma2(acc[kk * 4 + 3], p, c23.y);
                }
            }
            __syncthreads();
        }
        #pragma unroll
        for (int kk = 0; kk < 3; kk++)
            #pragma unroll
            for (int jp = 0; jp < 4; jp++)
                *(ull*)&Qs[(k0 + kk) * WS + j0 + jp * 2] = acc[kk * 4 + jp];
        __syncthreads();
        Qs[tid]       += pd[tid];
        Qs[tid + 256] += pd[tid + 256];
        __syncthreads();

        // --- Hann fold -> g_R[c] (RLEN/4 = 832 float4) ---
        const float W = 0.01227184630309f;   // 2*pi/512
        #pragma unroll
        for (int it = 0; it < 4; it++){
            int i4 = it * 256 + tid;
            if (i4 < RLEN / 4){
                int m  = i4 * 4;
                int k1 = m >> 8, j1 = m & 255;
                float c0 = __cosf((j1 + 0) * W);
                float c1 = __cosf((j1 + 1) * W);
                float c2 = __cosf((j1 + 2) * W);
                float c3 = __cosf((j1 + 3) * W);
                float4 o = {0.f, 0.f, 0.f, 0.f};
                if (k1 < KT){
                    float4 v1 = *(const float4*)&Qs[k1 * WS + j1];
                    o.x = 0.5f * (1.f - c0) * v1.x;
                    o.y = 0.5f * (1.f - c1) * v1.y;
                    o.z = 0.5f * (1.f - c2) * v1.z;
                    o.w = 0.5f * (1.f - c3) * v1.w;
                }
                if (k1 > 0){
                    float4 v2 = *(const float4*)&Qs[(k1 - 1) * WS + j1 + 256];
                    o.x += 0.5f * (1.f + c0) * v2.x;
                    o.y += 0.5f * (1.f + c1) * v2.y;
                    o.z += 0.5f * (1.f + c2) * v2.z;
                    o.w += 0.5f * (1.f + c3) * v2.w;
                }
                *(float4*)&g_R[(size_t)c * RLEN + m] = o;
            }
        }
        return;
    }

    // ======================= select branch =======================
    __shared__ __align__(16) float smV[256][8];
    __shared__ __align__(16) int   smI[256][8];
    __shared__ __align__(16) float sv[256];
    __shared__ __align__(16) int   si[256];
    __shared__ int   s_row, s_p;
    __shared__ float s_sum;
    const int b = bx;

    {
        float v0 = ctrl[b * NCP + tid];
        float v1 = ctrl[b * NCP + 256 + tid];
        float bv = v0; int bi = tid;
        if (better(v1, 256 + tid, bv, bi)){ bv = v1; bi = 256 + tid; }
        sv[tid] = bv; si[tid] = bi;
        for (int s = 128; s > 0; s >>= 1){
            __syncthreads();
            if (tid < s){
                float vo = sv[tid + s]; int io = si[tid + s];
                if (better(vo, io, sv[tid], si[tid])){ sv[tid] = vo; si[tid] = io; }
            }
        }
        __syncthreads();
        if (tid == 0) s_row = si[0];
        __syncthreads();
    }
    {
        sv[tid] = times[b * NF + tid]; si[tid] = tid;
        for (int s = 128; s > 0; s >>= 1){
            __syncthreads();
            if (tid < s){
                float vo = sv[tid + s]; int io = si[tid + s];
                if (better(vo, io, sv[tid], si[tid])){ sv[tid] = vo; si[tid] = io; }
            }
        }
        __syncthreads();
        if (tid == 0) s_p = si[0] * (NS / NF);
    }

    const float* row = lookup + (size_t)s_row * (CPD * NF);

    float tv[8]; int ti[8]; float es = 0.f;
    #pragma unroll
    for (int q = 0; q < 8; q++){ tv[q] = -FLT_MAX; ti[q] = 0x7fffffff; }
    for (int j = tid; j < CPD * NF; j += 256){
        float x = row[j];
        es += __expf(x);
        if (better(x, j, tv[7], ti[7])){
            tv[7] = x; ti[7] = j;
            #pragma unroll
            for (int q = 7; q > 0; q--){
                if (better(tv[q], ti[q], tv[q-1], ti[q-1])){
                    float fv = tv[q]; tv[q] = tv[q-1]; tv[q-1] = fv;
                    int   fi = ti[q]; ti[q] = ti[q-1]; ti[q-1] = fi;
                } else break;
            }
        }
    }
    #pragma unroll
    for (int q = 0; q < 8; q++){ smV[tid][q] = tv[q]; smI[tid][q] = ti[q]; }
    __syncthreads();
    sv[tid] = es;

    for (int s = 128; s > 0; s >>= 1){
        __syncthreads();
        if (tid < s){
            sv[tid] += sv[tid + s];
            int ia = 0, ib = 0;
            float ov[8]; int oi[8];
            #pragma unroll
            for (int t = 0; t < 8; t++){
                float va = smV[tid][ia];     int xa = smI[tid][ia];
                float vb = smV[tid + s][ib]; int xb = smI[tid + s][ib];
                bool pa = better(va, xa, vb, xb);
                ov[t] = pa ? va : vb; oi[t] = pa ? xa : xb;
                ia += pa ? 1 : 0; ib += pa ? 0 : 1;
            }
            #pragma unroll
            for (int t = 0; t < 8; t++){ smV[tid][t] = ov[t]; smI[tid][t] = oi[t]; }
        }
    }
    __syncthreads();
    if (tid == 0) s_sum = sv[0];
    __syncthreads();

    if (tid < 8){
        int idx = smI[0][tid];
        float val = __expf(smV[0][tid]) / s_sum;
        g_ic  [b * 8 + tid] = idx >> 8;
        g_ioff[b * 8 + tid] = s_p + (idx & 255) * HOP;
        g_iv  [b * 8 + tid] = val;
    }
}

// ============================================================================
// K2: out[b][n] = sum_i v_i * R[c_i][n - off_i]
//     2048 samples/block; unrolled 8-impulse loop with block-uniform guards
// ============================================================================
__global__ void __launch_bounds__(256) k_out(float* __restrict__ out){
    const int b   = blockIdx.y;
    const int tid = threadIdx.x;
    const int n0  = blockIdx.x * 2048;

    int   lc[8]; int loff[8]; float lv[8]; bool live[8];
    int any = 0;
    #pragma unroll
    for (int i = 0; i < 8; i++){
        loff[i] = __ldg(&g_ioff[b * 8 + i]);
        lc[i]   = __ldg(&g_ic  [b * 8 + i]);
        lv[i]   = __ldg(&g_iv  [b * 8 + i]);
        live[i] = (loff[i] < n0 + 2048) && (loff[i] + RLEN > n0);
        any    += live[i] ? 1 : 0;
    }

    #pragma unroll
    for (int q = 0; q < 2; q++){
        const int n = n0 + (q * 256 + tid) * 4;
        float4 acc = {0.f, 0.f, 0.f, 0.f};
        if (any){
            #pragma unroll
            for (int i = 0; i < 8; i++){
                if (live[i]){                        // block-uniform branch
                    int d = n - loff[i];
                    if (d >= 0 && d < RLEN){
                        float4 r = __ldg((const float4*)&g_R[(size_t)lc[i] * RLEN + d]);
                        float v = lv[i];
                        acc.x += v * r.x; acc.y += v * r.y;
                        acc.z += v * r.z; acc.w += v * r.w;
                    }
                }
            }
        }
        *(float4*)&out[(size_t)b * NS + n] = acc;
    }
}

// ============================================================================
extern "C" void kernel_launch(void* const* d_in, const int* in_sizes, int n_in,
                              void* d_out, int out_size)
{
    const float* ctrl   = (const float*)d_in[0];
    const float* times  = (const float*)d_in[1];
    const float* lookup = (const float*)d_in[2];
    const float* proj   = (const float*)d_in[3];
    const float* Amat   = (const float*)d_in[4];
    const float* Bm     = (const float*)d_in[5];
    const float* Cm     = (const float*)d_in[6];
    const float* Dm     = (const float*)d_in[7];
    float* out = (float*)d_out;
    (void)in_sizes; (void)n_in; (void)out_size;

    const int dynBytes = SM_TOT * sizeof(float);   // 106496 B
    cudaFuncSetAttribute(k_mega, cudaFuncAttributeMaxDynamicSharedMemorySize,
                         dynBytes);

    // Node 1: select (64 blocks) + full per-channel pipeline -> R (64 blocks)
    k_mega<<<128, 256, dynBytes>>>(ctrl, times, lookup, proj, Amat, Bm, Cm, Dm);

    // Node 2: shift-accumulate with register-resident live guards
    k_out<<<dim3(32, BATCH), 256>>>(out);
}